// round 11
// baseline (speedup 1.0000x reference)
#include <cuda_runtime.h>
#include <math.h>

// ---------------------------------------------------------------------------
// YoloLoss v4: latency-bound -> throughput-bound restructure.
//   - ALL loads unconditional and mutually independent (no gating branch):
//       pred  : block-staged to smem, 8x coalesced LDG.128 per thread
//       tcls  : block-staged to smem, 5x coalesced LDG.128 per thread
//       tbox  : per-thread LDG.128 (16B/cell -> naturally coalesced)
//       obj   : per-thread load (dtype auto-detected)
//   - compute fully predicated (w_obj / w_noobj weights), zero divergence
//   - block partials -> global double atomics -> last-block finalize
// ---------------------------------------------------------------------------

#define S_INV (1.0f / 14.0f)
#define CPB   256

// acc[0]=n_obj, [1]=cls, [2]=noobj, [3]=reg, [4]=conf. Zero-initialized; the
// finalizing block restores them to zero (deterministic across graph replays).
__device__ double g_acc[5];
__device__ unsigned int g_done;

__device__ __forceinline__ float iou_xyxy(
    float x1, float y1, float x2, float y2,
    float tx1, float ty1, float tx2, float ty2)
{
    float lx = fmaxf(x1, tx1), ly = fmaxf(y1, ty1);
    float rx = fminf(x2, tx2), ry = fminf(y2, ty2);
    float w = fmaxf(rx - lx, 0.0f), h = fmaxf(ry - ly, 0.0f);
    float inter = w * h;
    float a1 = (x2 - x1) * (y2 - y1);
    float a2 = (tx2 - tx1) * (ty2 - ty1);
    return inter / (a1 + a2 - inter);
}

__global__ void __launch_bounds__(256)
yolo_fused(const float* __restrict__ pred,
           const float* __restrict__ tbox,
           const float* __restrict__ tcls,
           const void*  __restrict__ objp,
           float* __restrict__ out,
           int ncells, float Nf, int nblocks)
{
    __shared__ __align__(16) float sp[CPB * 30];   // 30720 B staged pred
    __shared__ __align__(16) float st[CPB * 20];   // 20480 B staged target_cls

    int tid = threadIdx.x;
    int cb  = blockIdx.x * CPB;
    int ncell_blk = min(CPB, ncells - cb);
    bool full = (ncell_blk == CPB);

    // ---- issue ALL independent global loads up front -----------------------
    const float4* gp = (const float4*)(pred + (size_t)cb * 30);
    const float4* gt = (const float4*)(tcls + (size_t)cb * 20);

    if (full) {
        // pred: 1920 float4s -> 7 full rounds + half round
        #pragma unroll
        for (int k = 0; k < 7; k++)
            ((float4*)sp)[tid + k * 256] = gp[tid + k * 256];
        if (tid < 128)
            ((float4*)sp)[tid + 1792] = gp[tid + 1792];
        // tcls: 1280 float4s -> 5 full rounds
        #pragma unroll
        for (int k = 0; k < 5; k++)
            ((float4*)st)[tid + k * 256] = gt[tid + k * 256];
    } else {
        int nf = ncell_blk * 30;
        int n4 = nf >> 2;
        for (int idx = tid; idx < n4; idx += 256)
            ((float4*)sp)[idx] = gp[idx];
        if ((nf & 3) && tid == 0)
            ((float2*)sp)[n4 * 2] = ((const float2*)gp)[n4 * 2];
        int n4t = ncell_blk * 5;
        for (int idx = tid; idx < n4t; idx += 256)
            ((float4*)st)[idx] = gt[idx];
    }

    // independent per-thread loads (coalesced): tbox + obj + dtype prefix
    int i  = cb + tid;
    int ic = min(i, ncells - 1);                   // clamp for safe loads
    bool act = (tid < ncell_blk);

    float4 tb = ((const float4*)tbox)[ic];

    //   float32 1.0f = 00 00 80 3F : byte with bits above 1     -> gt1
    //   uint8   0/1  : nonzero byte at offset %4 != 0           -> off4
    //   int32   0/1  : nonzero only at byte offset %4 == 0      -> neither
    uint4 w = ((const uint4*)objp)[tid];
    unsigned v_all = w.x | w.y | w.z | w.w;
    int gt1  = __syncthreads_or((v_all & 0xFEFEFEFEu) != 0);
    int off4 = __syncthreads_or((v_all & 0xFFFFFF00u) != 0);

    float obj;
    if (gt1)       obj = ((const float*)objp)[ic];
    else if (off4) obj = (float)((const unsigned char*)objp)[ic];
    else           obj = (float)((const int*)objp)[ic];

    __syncthreads();                               // staged data visible

    // ---- branch-free predicated compute ------------------------------------
    float w_obj = (act && obj > 0.5f) ? 1.0f : 0.0f;
    float w_no  = act ? (1.0f - w_obj) : 0.0f;

    const float* p = sp + tid * 30;                // conflict-free LDS
    float2 a0 = *(const float2*)(p + 0);
    float2 a1 = *(const float2*)(p + 2);
    float2 a2 = *(const float2*)(p + 4);
    float2 a3 = *(const float2*)(p + 6);
    float2 a4 = *(const float2*)(p + 8);

    float b1x = a0.x, b1y = a0.y, b1w = a1.x, b1h = a1.y, b1c = a2.x;
    float b2x = a2.y, b2y = a3.x, b2w = a3.y, b2h = a4.x, b2c = a4.y;

    // noobj term
    float v_noobj = w_no * (b1x*b1x + b1y*b1y + b1w*b1w + b1h*b1h + b1c*b1c
                          + b2x*b2x + b2y*b2y + b2w*b2w + b2h*b2h + b2c*b2c);

    // obj terms (always computed; inputs are always valid data)
    float tcx = tb.x * S_INV, tcy = tb.y * S_INV;
    float tx1 = tcx - 0.5f * tb.z, ty1 = tcy - 0.5f * tb.w;
    float tx2 = tcx + 0.5f * tb.z, ty2 = tcy + 0.5f * tb.w;

    float c1x = b1x * S_INV, c1y = b1y * S_INV;
    float c2x = b2x * S_INV, c2y = b2y * S_INV;

    float iou1 = iou_xyxy(c1x - 0.5f * b1w, c1y - 0.5f * b1h,
                          c1x + 0.5f * b1w, c1y + 0.5f * b1h,
                          tx1, ty1, tx2, ty2);
    float iou2 = iou_xyxy(c2x - 0.5f * b2w, c2y - 0.5f * b2h,
                          c2x + 0.5f * b2w, c2y + 0.5f * b2h,
                          tx1, ty1, tx2, ty2);

    bool take1 = (iou1 >= iou2);
    float bx = take1 ? b1x : b2x;
    float by = take1 ? b1y : b2y;
    float bw = take1 ? b1w : b2w;
    float bh = take1 ? b1h : b2h;
    float bc = take1 ? b1c : b2c;
    float biou = take1 ? iou1 : iou2;

    float dx = bx - tb.x;
    float dy = by - tb.y;
    float dw = sqrtf(bw) - sqrtf(tb.z);
    float dh = sqrtf(bh) - sqrtf(tb.w);
    float v_reg  = w_obj * (dx*dx + dy*dy + dw*dw + dh*dh);
    float dc = bc - biou;
    float v_conf = w_obj * (dc * dc);
    float v_nobj = w_obj;

    // class loss from smem (both operands staged)
    const float2* pc = (const float2*)(p + 10);
    const float4* tc = (const float4*)(st + tid * 20);
    float s = 0.0f;
    #pragma unroll
    for (int j = 0; j < 5; j++) {
        float4 t  = tc[j];
        float2 c0 = pc[2 * j];
        float2 c1 = pc[2 * j + 1];
        float d0 = c0.x - t.x, d1 = c0.y - t.y;
        float d2 = c1.x - t.z, d3 = c1.y - t.w;
        s += d0 * d0 + d1 * d1 + d2 * d2 + d3 * d3;
    }
    float v_cls = w_obj * s;

    // ---- block reduction ----------------------------------------------------
    const unsigned m = 0xffffffffu;
    #pragma unroll
    for (int off = 16; off > 0; off >>= 1) {
        v_nobj  += __shfl_down_sync(m, v_nobj,  off);
        v_cls   += __shfl_down_sync(m, v_cls,   off);
        v_noobj += __shfl_down_sync(m, v_noobj, off);
        v_reg   += __shfl_down_sync(m, v_reg,   off);
        v_conf  += __shfl_down_sync(m, v_conf,  off);
    }

    __shared__ double sacc[5];
    if (tid < 5) sacc[tid] = 0.0;
    __syncthreads();
    if ((tid & 31) == 0) {
        atomicAdd(&sacc[0], (double)v_nobj);
        atomicAdd(&sacc[1], (double)v_cls);
        atomicAdd(&sacc[2], (double)v_noobj);
        atomicAdd(&sacc[3], (double)v_reg);
        atomicAdd(&sacc[4], (double)v_conf);
    }
    __syncthreads();
    if (tid < 5)
        atomicAdd(&g_acc[tid], sacc[tid]);

    // ---- last-block finalize -------------------------------------------------
    __threadfence();
    __shared__ unsigned int ticket;
    if (tid == 0) ticket = atomicAdd(&g_done, 1u);
    __syncthreads();
    if (ticket == (unsigned)(nblocks - 1) && tid == 0) {
        __threadfence();
        double n_obj   = g_acc[0];
        double n_noobj = (double)ncells - n_obj;
        double cls   = g_acc[1] / (double)Nf;
        double noobj = 0.5 * g_acc[2] / n_noobj;
        double reg   = 5.0 * g_acc[3] / n_obj;
        double conf  = g_acc[4] / n_obj;
        out[0] = (float)(reg + conf + noobj + cls);
        out[1] = (float)reg;
        out[2] = (float)conf;
        out[3] = (float)noobj;
        out[4] = (float)cls;
        g_acc[0] = 0.0; g_acc[1] = 0.0; g_acc[2] = 0.0;
        g_acc[3] = 0.0; g_acc[4] = 0.0;
        g_done = 0u;
    }
}

extern "C" void kernel_launch(void* const* d_in, const int* in_sizes, int n_in,
                              void* d_out, int out_size)
{
    const float* pred = (const float*)d_in[0];
    const float* tbox = (const float*)d_in[1];
    const float* tcls = (const float*)d_in[2];
    const void*  objp = d_in[3];

    int ncells = in_sizes[1] / 4;              // target_boxes: 4 floats/cell
    int nbatch = in_sizes[0] / (14 * 14 * 30);
    int nblocks = (ncells + CPB - 1) / CPB;    // 3136 for reference shape

    yolo_fused<<<nblocks, CPB>>>(pred, tbox, tcls, objp,
                                 (float*)d_out, ncells, (float)nbatch, nblocks);
}

// round 12
// speedup vs baseline: 1.3082x; 1.3082x over previous
#include <cuda_runtime.h>
#include <math.h>

// ---------------------------------------------------------------------------
// YoloLoss v5: R8's gated-load structure + deep per-thread batching.
//   - 8 cells/thread (2048 cells/block, 392 blocks): amortizes the block
//     epilogue (shuffle tree, barriers, atomics, ticket) 8x vs R8
//   - obj values for all 8 cells preloaded (front-batched independent loads)
//   - pred loaded unconditionally per cell; tbox/tcls gated on obj (~70% of
//     cells skip them entirely -> sector savings + skips iou/sqrt/div MUFU)
//   - block reduce: warp shuffles -> per-warp float4+float smem stores ->
//     5 lanes sum 8 warps (no double smem atomics / CAS loops)
//   - 5 global double atomics per block (392 blocks: negligible)
// ---------------------------------------------------------------------------

#define S_INV (1.0f / 14.0f)
#define TPB   256
#define CPT   8                       // cells per thread
#define CPB   (TPB * CPT)             // 2048 cells per block

// acc[0]=n_obj, [1]=cls, [2]=noobj, [3]=reg, [4]=conf. Zero-initialized; the
// finalizing block restores them to zero (deterministic across graph replays).
__device__ double g_acc[5];
__device__ unsigned int g_done;

__device__ __forceinline__ float iou_xyxy(
    float x1, float y1, float x2, float y2,
    float tx1, float ty1, float tx2, float ty2)
{
    float lx = fmaxf(x1, tx1), ly = fmaxf(y1, ty1);
    float rx = fminf(x2, tx2), ry = fminf(y2, ty2);
    float w = fmaxf(rx - lx, 0.0f), h = fmaxf(ry - ly, 0.0f);
    float inter = w * h;
    float a1 = (x2 - x1) * (y2 - y1);
    float a2 = (tx2 - tx1) * (ty2 - ty1);
    return inter / (a1 + a2 - inter);
}

__global__ void __launch_bounds__(TPB, 6)
yolo_fused(const float* __restrict__ pred,
           const float* __restrict__ tbox,
           const float* __restrict__ tcls,
           const void*  __restrict__ objp,
           float* __restrict__ out,
           int ncells, float Nf, int nblocks)
{
    int tid  = threadIdx.x;
    int tile = blockIdx.x * CPB;

    // ---- dtype detection from 4KB prefix (one uint4 per thread) -----------
    //   float32 1.0f = 00 00 80 3F : byte with bits above 1     -> gt1
    //   uint8   0/1  : nonzero byte at offset %4 != 0           -> off4
    //   int32   0/1  : nonzero only at byte offset %4 == 0      -> neither
    uint4 wdet = ((const uint4*)objp)[tid];
    unsigned v_all = wdet.x | wdet.y | wdet.z | wdet.w;
    int gt1  = __syncthreads_or((v_all & 0xFEFEFEFEu) != 0);
    int off4 = __syncthreads_or((v_all & 0xFFFFFF00u) != 0);

    // ---- preload obj for all 8 cells (independent, front-batched) ---------
    float objv[CPT];
    #pragma unroll
    for (int k = 0; k < CPT; k++) {
        int i  = tile + k * TPB + tid;
        int ic = min(i, ncells - 1);
        if (gt1)       objv[k] = ((const float*)objp)[ic];
        else if (off4) objv[k] = (float)((const unsigned char*)objp)[ic];
        else           objv[k] = (float)((const int*)objp)[ic];
    }

    // ---- main 8-cell loop ---------------------------------------------------
    float v_nobj = 0.0f, v_cls = 0.0f, v_noobj = 0.0f, v_reg = 0.0f, v_conf = 0.0f;

    #pragma unroll
    for (int k = 0; k < CPT; k++) {
        int i = tile + k * TPB + tid;
        bool valid = (i < ncells);
        int ic = min(i, ncells - 1);

        // pred: unconditional (whole tensor is needed either way)
        const float* p = pred + (size_t)ic * 30;
        float2 a0 = *(const float2*)(p + 0);
        float2 a1 = *(const float2*)(p + 2);
        float2 a2 = *(const float2*)(p + 4);
        float2 a3 = *(const float2*)(p + 6);
        float2 a4 = *(const float2*)(p + 8);

        if (!valid) continue;

        if (objv[k] > 0.5f) {
            v_nobj += 1.0f;

            float4 tb = ((const float4*)tbox)[ic];
            float tcx = tb.x * S_INV, tcy = tb.y * S_INV;
            float tx1 = tcx - 0.5f * tb.z, ty1 = tcy - 0.5f * tb.w;
            float tx2 = tcx + 0.5f * tb.z, ty2 = tcy + 0.5f * tb.w;

            float b1x = a0.x, b1y = a0.y, b1w = a1.x, b1h = a1.y, b1c = a2.x;
            float b2x = a2.y, b2y = a3.x, b2w = a3.y, b2h = a4.x, b2c = a4.y;

            float c1x = b1x * S_INV, c1y = b1y * S_INV;
            float c2x = b2x * S_INV, c2y = b2y * S_INV;

            float iou1 = iou_xyxy(c1x - 0.5f * b1w, c1y - 0.5f * b1h,
                                  c1x + 0.5f * b1w, c1y + 0.5f * b1h,
                                  tx1, ty1, tx2, ty2);
            float iou2 = iou_xyxy(c2x - 0.5f * b2w, c2y - 0.5f * b2h,
                                  c2x + 0.5f * b2w, c2y + 0.5f * b2h,
                                  tx1, ty1, tx2, ty2);

            bool take1 = (iou1 >= iou2);
            float bx = take1 ? b1x : b2x;
            float by = take1 ? b1y : b2y;
            float bw = take1 ? b1w : b2w;
            float bh = take1 ? b1h : b2h;
            float bc = take1 ? b1c : b2c;
            float biou = take1 ? iou1 : iou2;

            float dx = bx - tb.x;
            float dy = by - tb.y;
            float dw = sqrtf(bw) - sqrtf(tb.z);
            float dh = sqrtf(bh) - sqrtf(tb.w);
            v_reg += dx * dx + dy * dy + dw * dw + dh * dh;

            float dc = bc - biou;
            v_conf += dc * dc;

            // class loss: only for obj cells (traffic + MUFU savings)
            const float2* pc = (const float2*)(p + 10);
            const float4* tc = (const float4*)(tcls + (size_t)ic * 20);
            float s = 0.0f;
            #pragma unroll
            for (int j = 0; j < 5; j++) {
                float4 t  = tc[j];
                float2 c0 = pc[2 * j];
                float2 c1 = pc[2 * j + 1];
                float d0 = c0.x - t.x, d1 = c0.y - t.y;
                float d2 = c1.x - t.z, d3 = c1.y - t.w;
                s += d0 * d0 + d1 * d1 + d2 * d2 + d3 * d3;
            }
            v_cls += s;
        } else {
            v_noobj += a0.x * a0.x + a0.y * a0.y + a1.x * a1.x + a1.y * a1.y
                     + a2.x * a2.x + a2.y * a2.y + a3.x * a3.x + a3.y * a3.y
                     + a4.x * a4.x + a4.y * a4.y;
        }
    }

    // ---- block reduction (no smem atomics) ---------------------------------
    const unsigned m = 0xffffffffu;
    #pragma unroll
    for (int off = 16; off > 0; off >>= 1) {
        v_nobj  += __shfl_down_sync(m, v_nobj,  off);
        v_cls   += __shfl_down_sync(m, v_cls,   off);
        v_noobj += __shfl_down_sync(m, v_noobj, off);
        v_reg   += __shfl_down_sync(m, v_reg,   off);
        v_conf  += __shfl_down_sync(m, v_conf,  off);
    }

    __shared__ float swarp[8][8];      // [warp][0..4 used], padded row of 8
    int wid = tid >> 5;
    if ((tid & 31) == 0) {
        swarp[wid][0] = v_nobj;
        swarp[wid][1] = v_cls;
        swarp[wid][2] = v_noobj;
        swarp[wid][3] = v_reg;
        swarp[wid][4] = v_conf;
    }
    __syncthreads();

    if (tid < 5) {
        float s = 0.0f;
        #pragma unroll
        for (int wj = 0; wj < 8; wj++) s += swarp[wj][tid];
        atomicAdd(&g_acc[tid], (double)s);
    }

    // ---- last-block finalize ------------------------------------------------
    __threadfence();
    __shared__ unsigned int ticket;
    if (tid == 0) ticket = atomicAdd(&g_done, 1u);
    __syncthreads();
    if (ticket == (unsigned)(nblocks - 1) && tid == 0) {
        __threadfence();
        double n_obj   = g_acc[0];
        double n_noobj = (double)ncells - n_obj;
        double cls   = g_acc[1] / (double)Nf;
        double noobj = 0.5 * g_acc[2] / n_noobj;
        double reg   = 5.0 * g_acc[3] / n_obj;
        double conf  = g_acc[4] / n_obj;
        out[0] = (float)(reg + conf + noobj + cls);
        out[1] = (float)reg;
        out[2] = (float)conf;
        out[3] = (float)noobj;
        out[4] = (float)cls;
        g_acc[0] = 0.0; g_acc[1] = 0.0; g_acc[2] = 0.0;
        g_acc[3] = 0.0; g_acc[4] = 0.0;
        g_done = 0u;
    }
}

extern "C" void kernel_launch(void* const* d_in, const int* in_sizes, int n_in,
                              void* d_out, int out_size)
{
    const float* pred = (const float*)d_in[0];
    const float* tbox = (const float*)d_in[1];
    const float* tcls = (const float*)d_in[2];
    const void*  objp = d_in[3];

    int ncells = in_sizes[1] / 4;              // target_boxes: 4 floats/cell
    int nbatch = in_sizes[0] / (14 * 14 * 30);
    int nblocks = (ncells + CPB - 1) / CPB;    // 392 for reference shape

    yolo_fused<<<nblocks, TPB>>>(pred, tbox, tcls, objp,
                                 (float*)d_out, ncells, (float)nbatch, nblocks);
}

// round 14
// speedup vs baseline: 1.6729x; 1.2788x over previous
#include <cuda_runtime.h>
#include <math.h>
#include <stdint.h>

// ---------------------------------------------------------------------------
// YoloLoss v6: TMA-streamed (cp.async.bulk) double-buffered pipeline.
//   - pred (120B/cell) + tbox (16B/cell) are contiguous per 128-cell tile ->
//     one bulk copy each per tile; copy-engine supplies the MLP that the
//     SM-side LDG path could not (R8/R10/R12 all pinned at ~3.4 TB/s).
//   - tcls gated-scattered LDG (sparsity saving), obj preloaded x8.
//   - 2-stage smem pipeline w/ mbarrier expect_tx / parity waits.
//   - warp-shuffle reduce -> 5 global f64 atomics -> last-block finalize.
// ---------------------------------------------------------------------------

#define S_INV (1.0f / 14.0f)
#define TPB   128
#define TILE  128                  // cells per tile (== TPB)
#define NT    8                    // tiles per block

#define PRED_TILE_B (TILE * 30 * 4)   // 15360 bytes
#define TBOX_TILE_B (TILE * 4 * 4)    // 2048 bytes
#define TX_BYTES    (PRED_TILE_B + TBOX_TILE_B)

// acc[0]=n_obj, [1]=cls, [2]=noobj, [3]=reg, [4]=conf. Zero-initialized; the
// finalizing block restores them to zero (deterministic across graph replays).
__device__ double g_acc[5];
__device__ unsigned int g_done;

// ---- PTX helpers -----------------------------------------------------------
__device__ __forceinline__ unsigned smem_u32(const void* p) {
    return (unsigned)__cvta_generic_to_shared(p);
}
__device__ __forceinline__ unsigned long long gaddr(const void* p) {
    unsigned long long g;
    asm("cvta.to.global.u64 %0, %1;" : "=l"(g) : "l"(p));
    return g;
}
__device__ __forceinline__ void mbar_init(unsigned a, unsigned cnt) {
    asm volatile("mbarrier.init.shared.b64 [%0], %1;" :: "r"(a), "r"(cnt) : "memory");
}
__device__ __forceinline__ void mbar_expect_tx(unsigned a, unsigned bytes) {
    asm volatile("mbarrier.arrive.expect_tx.shared.b64 _, [%0], %1;"
                 :: "r"(a), "r"(bytes) : "memory");
}
__device__ __forceinline__ void bulk_g2s(unsigned dst, unsigned long long src,
                                         unsigned bytes, unsigned bar) {
    asm volatile(
        "cp.async.bulk.shared::cluster.global.mbarrier::complete_tx::bytes "
        "[%0], [%1], %2, [%3];"
        :: "r"(dst), "l"(src), "r"(bytes), "r"(bar) : "memory");
}
__device__ __forceinline__ void mbar_wait(unsigned a, unsigned phase) {
    unsigned done;
    asm volatile(
        "{\n\t.reg .pred p;\n\t"
        "mbarrier.try_wait.parity.acquire.cta.shared::cta.b64 p, [%1], %2;\n\t"
        "selp.b32 %0, 1, 0, p;\n\t}"
        : "=r"(done) : "r"(a), "r"(phase) : "memory");
    if (!done) {
        asm volatile(
            "{\n\t.reg .pred P1;\n\t"
            "W%=:\n\t"
            "mbarrier.try_wait.parity.acquire.cta.shared::cta.b64 P1, [%0], %1, 0x989680;\n\t"
            "@P1 bra.uni D%=;\n\t"
            "bra.uni W%=;\n\t"
            "D%=:\n\t}"
            :: "r"(a), "r"(phase) : "memory");
    }
}
__device__ __forceinline__ void fence_proxy_async_smem() {
    asm volatile("fence.proxy.async.shared::cta;" ::: "memory");
}

// ---- math -------------------------------------------------------------------
__device__ __forceinline__ float iou_xyxy(
    float x1, float y1, float x2, float y2,
    float tx1, float ty1, float tx2, float ty2)
{
    float lx = fmaxf(x1, tx1), ly = fmaxf(y1, ty1);
    float rx = fminf(x2, tx2), ry = fminf(y2, ty2);
    float w = fmaxf(rx - lx, 0.0f), h = fmaxf(ry - ly, 0.0f);
    float inter = w * h;
    float a1 = (x2 - x1) * (y2 - y1);
    float a2 = (tx2 - tx1) * (ty2 - ty1);
    return inter / (a1 + a2 - inter);
}

// prow: 30 floats (smem or global; inlined per call site), tb: target box,
// tcrow: target_cls row in global (only touched when obj).
__device__ __forceinline__ void cell_compute(
    const float* __restrict__ prow, float4 tb,
    const float* __restrict__ tcrow, float obj,
    float& v_nobj, float& v_cls, float& v_noobj, float& v_reg, float& v_conf)
{
    float2 a0 = *(const float2*)(prow + 0);
    float2 a1 = *(const float2*)(prow + 2);
    float2 a2 = *(const float2*)(prow + 4);
    float2 a3 = *(const float2*)(prow + 6);
    float2 a4 = *(const float2*)(prow + 8);

    if (obj > 0.5f) {
        v_nobj += 1.0f;

        float tcx = tb.x * S_INV, tcy = tb.y * S_INV;
        float tx1 = tcx - 0.5f * tb.z, ty1 = tcy - 0.5f * tb.w;
        float tx2 = tcx + 0.5f * tb.z, ty2 = tcy + 0.5f * tb.w;

        float b1x = a0.x, b1y = a0.y, b1w = a1.x, b1h = a1.y, b1c = a2.x;
        float b2x = a2.y, b2y = a3.x, b2w = a3.y, b2h = a4.x, b2c = a4.y;

        float c1x = b1x * S_INV, c1y = b1y * S_INV;
        float c2x = b2x * S_INV, c2y = b2y * S_INV;

        float iou1 = iou_xyxy(c1x - 0.5f * b1w, c1y - 0.5f * b1h,
                              c1x + 0.5f * b1w, c1y + 0.5f * b1h,
                              tx1, ty1, tx2, ty2);
        float iou2 = iou_xyxy(c2x - 0.5f * b2w, c2y - 0.5f * b2h,
                              c2x + 0.5f * b2w, c2y + 0.5f * b2h,
                              tx1, ty1, tx2, ty2);

        bool take1 = (iou1 >= iou2);
        float bx = take1 ? b1x : b2x;
        float by = take1 ? b1y : b2y;
        float bw = take1 ? b1w : b2w;
        float bh = take1 ? b1h : b2h;
        float bc = take1 ? b1c : b2c;
        float biou = take1 ? iou1 : iou2;

        float dx = bx - tb.x;
        float dy = by - tb.y;
        float dw = sqrtf(bw) - sqrtf(tb.z);
        float dh = sqrtf(bh) - sqrtf(tb.w);
        v_reg += dx * dx + dy * dy + dw * dw + dh * dh;

        float dc = bc - biou;
        v_conf += dc * dc;

        const float2* pc = (const float2*)(prow + 10);
        const float4* tc = (const float4*)tcrow;    // 80B/cell -> 16B aligned
        float s = 0.0f;
        #pragma unroll
        for (int j = 0; j < 5; j++) {
            float4 t  = tc[j];
            float2 c0 = pc[2 * j];
            float2 c1 = pc[2 * j + 1];
            float d0 = c0.x - t.x, d1 = c0.y - t.y;
            float d2 = c1.x - t.z, d3 = c1.y - t.w;
            s += d0 * d0 + d1 * d1 + d2 * d2 + d3 * d3;
        }
        v_cls += s;
    } else {
        v_noobj += a0.x * a0.x + a0.y * a0.y + a1.x * a1.x + a1.y * a1.y
                 + a2.x * a2.x + a2.y * a2.y + a3.x * a3.x + a3.y * a3.y
                 + a4.x * a4.x + a4.y * a4.y;
    }
}

__global__ void __launch_bounds__(TPB)
yolo_fused(const float* __restrict__ pred,
           const float* __restrict__ tbox,
           const float* __restrict__ tcls,
           const void*  __restrict__ objp,
           float* __restrict__ out,
           int ncells, float Nf)
{
    __shared__ __align__(16) float sp[2][TILE * 30];   // 2 x 15360 B pred
    __shared__ __align__(16) float sb[2][TILE * 4];    // 2 x  2048 B tbox
    __shared__ __align__(8)  unsigned long long mbar_store[2];

    int tid = threadIdx.x;
    unsigned mb[2] = { smem_u32(&mbar_store[0]), smem_u32(&mbar_store[1]) };

    if (tid == 0) {
        mbar_init(mb[0], 1);
        mbar_init(mb[1], 1);
        fence_proxy_async_smem();      // init visible to async proxy
    }

    // ---- dtype detection from 2KB prefix ----------------------------------
    //   float32 1.0f = 00 00 80 3F : byte with bits above 1     -> gt1
    //   uint8   0/1  : nonzero byte at offset %4 != 0           -> off4
    //   int32   0/1  : nonzero only at byte offset %4 == 0      -> neither
    unsigned v_all = 0;
    if ((tid + 1) * 16 <= ncells) {    // safe even if obj stored as uint8
        uint4 w = ((const uint4*)objp)[tid];
        v_all = w.x | w.y | w.z | w.w;
    }
    int gt1  = __syncthreads_or((v_all & 0xFEFEFEFEu) != 0);
    int off4 = __syncthreads_or((v_all & 0xFFFFFF00u) != 0);
    // (the barriers above also publish mbar_init to all threads)

    int ntiles_full = ncells / TILE;
    int tile0 = blockIdx.x * NT;

    // ---- preload obj for all NT tiles (independent loads) ------------------
    float objv[NT];
    #pragma unroll
    for (int k = 0; k < NT; k++) {
        int i  = (tile0 + k) * TILE + tid;
        int ic = min(i, ncells - 1);
        if (gt1)       objv[k] = ((const float*)objp)[ic];
        else if (off4) objv[k] = (float)((const unsigned char*)objp)[ic];
        else           objv[k] = (float)((const int*)objp)[ic];
    }

    // ---- prologue: fill both stages ----------------------------------------
    if (tid == 0) {
        #pragma unroll
        for (int s = 0; s < 2; s++) {
            int gt = tile0 + s;
            if (gt < ntiles_full) {
                mbar_expect_tx(mb[s], TX_BYTES);
                bulk_g2s(smem_u32(&sp[s][0]),
                         gaddr(pred + (size_t)gt * TILE * 30), PRED_TILE_B, mb[s]);
                bulk_g2s(smem_u32(&sb[s][0]),
                         gaddr(tbox + (size_t)gt * TILE * 4),  TBOX_TILE_B, mb[s]);
            }
        }
    }

    float v_nobj = 0.0f, v_cls = 0.0f, v_noobj = 0.0f, v_reg = 0.0f, v_conf = 0.0f;
    int fp0 = 0, fp1 = 0;

    #pragma unroll
    for (int t = 0; t < NT; t++) {
        int gt = tile0 + t;
        if (gt * TILE >= ncells) break;            // uniform across block
        int s = t & 1;

        if (gt < ntiles_full) {
            // full tile: pipelined smem path
            int ph = s ? fp1 : fp0;
            mbar_wait(mb[s], ph);
            if (s) fp1 ^= 1; else fp0 ^= 1;

            int i = gt * TILE + tid;               // always < ncells here
            float4 tb = ((const float4*)&sb[s][0])[tid];
            cell_compute(&sp[s][tid * 30], tb,
                         tcls + (size_t)i * 20, objv[t],
                         v_nobj, v_cls, v_noobj, v_reg, v_conf);

            __syncthreads();                       // all lanes done with buf s
            if (tid == 0) {
                int gt2 = gt + 2;
                if (t + 2 < NT && gt2 < ntiles_full) {
                    fence_proxy_async_smem();      // order reads before overwrite
                    mbar_expect_tx(mb[s], TX_BYTES);
                    bulk_g2s(smem_u32(&sp[s][0]),
                             gaddr(pred + (size_t)gt2 * TILE * 30), PRED_TILE_B, mb[s]);
                    bulk_g2s(smem_u32(&sb[s][0]),
                             gaddr(tbox + (size_t)gt2 * TILE * 4),  TBOX_TILE_B, mb[s]);
                }
            }
        } else {
            // ragged tail tile: direct global loads (cold path)
            int i = gt * TILE + tid;
            if (i < ncells) {
                float4 tb = ((const float4*)tbox)[i];
                cell_compute(pred + (size_t)i * 30, tb,
                             tcls + (size_t)i * 20, objv[t],
                             v_nobj, v_cls, v_noobj, v_reg, v_conf);
            }
        }
    }

    // ---- block reduction (4 warps, no smem atomics) -------------------------
    const unsigned m = 0xffffffffu;
    #pragma unroll
    for (int off = 16; off > 0; off >>= 1) {
        v_nobj  += __shfl_down_sync(m, v_nobj,  off);
        v_cls   += __shfl_down_sync(m, v_cls,   off);
        v_noobj += __shfl_down_sync(m, v_noobj, off);
        v_reg   += __shfl_down_sync(m, v_reg,   off);
        v_conf  += __shfl_down_sync(m, v_conf,  off);
    }

    __shared__ float swarp[4][8];
    int wid = tid >> 5;
    if ((tid & 31) == 0) {
        swarp[wid][0] = v_nobj;
        swarp[wid][1] = v_cls;
        swarp[wid][2] = v_noobj;
        swarp[wid][3] = v_reg;
        swarp[wid][4] = v_conf;
    }
    __syncthreads();

    if (tid < 5) {
        float s = swarp[0][tid] + swarp[1][tid] + swarp[2][tid] + swarp[3][tid];
        atomicAdd(&g_acc[tid], (double)s);
    }

    // ---- last-block finalize -------------------------------------------------
    __threadfence();
    __shared__ unsigned int ticket;
    if (tid == 0) ticket = atomicAdd(&g_done, 1u);
    __syncthreads();
    if (ticket == gridDim.x - 1 && tid == 0) {
        __threadfence();
        double n_obj   = g_acc[0];
        double n_noobj = (double)ncells - n_obj;
        double cls   = g_acc[1] / (double)Nf;
        double noobj = 0.5 * g_acc[2] / n_noobj;
        double reg   = 5.0 * g_acc[3] / n_obj;
        double conf  = g_acc[4] / n_obj;
        out[0] = (float)(reg + conf + noobj + cls);
        out[1] = (float)reg;
        out[2] = (float)conf;
        out[3] = (float)noobj;
        out[4] = (float)cls;
        g_acc[0] = 0.0; g_acc[1] = 0.0; g_acc[2] = 0.0;
        g_acc[3] = 0.0; g_acc[4] = 0.0;
        g_done = 0u;
    }
}

extern "C" void kernel_launch(void* const* d_in, const int* in_sizes, int n_in,
                              void* d_out, int out_size)
{
    const float* pred = (const float*)d_in[0];
    const float* tbox = (const float*)d_in[1];
    const float* tcls = (const float*)d_in[2];
    const void*  objp = d_in[3];

    int ncells = in_sizes[1] / 4;                  // target_boxes: 4 floats/cell
    int nbatch = in_sizes[0] / (14 * 14 * 30);
    int ntiles = (ncells + TILE - 1) / TILE;       // 6272 for reference shape
    int nblocks = (ntiles + NT - 1) / NT;          // 784

    yolo_fused<<<nblocks, TPB>>>(pred, tbox, tcls, objp,
                                 (float*)d_out, ncells, (float)nbatch);
}